// round 1
// baseline (speedup 1.0000x reference)
#include <cuda_runtime.h>

// ReactDiffDynamics: for each batch b (64), channels U,V of 512x512 fp32:
//   dUdt = a*lap(U) + U - U^3 - k - V
//   dVdt = b*lap(V) + U - V
// lap = 5-point periodic stencil / dx^2, dx = 0.06451612903 (=1/15.5).
//
// Inputs (metadata order): d_in[0]=t (1 fp32, unused), d_in[1]=x (64*2*512*512 fp32),
// d_in[2]=params (64*3 fp32). Output: same shape as x.
//
// One thread computes a float4 group (4 contiguous x positions) for BOTH channels.
// Total threads = 64 * 512 * (512/4) = 2^22 exactly.

#define RD_W 512
#define RD_H 512
#define RD_HW (RD_W * RD_H)

__global__ __launch_bounds__(256) void react_diff_kernel(
    const float* __restrict__ x,
    const float* __restrict__ params,
    float* __restrict__ out)
{
    const float inv_dx2 = 1.0f / (0.06451612903f * 0.06451612903f); // 240.25

    int gid = blockIdx.x * blockDim.x + threadIdx.x; // 0 .. 2^22-1
    int xq = gid & 127;          // float4 group within row (W/4 = 128)
    int y  = (gid >> 7) & 511;   // row
    int b  = gid >> 16;          // batch (128*512 = 65536)

    const float* Ubase = x + (size_t)b * 2 * RD_HW;
    const float* Vbase = Ubase + RD_HW;
    float* OUbase = out + (size_t)b * 2 * RD_HW;
    float* OVbase = OUbase + RD_HW;

    int ym = (y - 1) & 511;
    int yp = (y + 1) & 511;
    int x0 = xq << 2;
    int xl = (x0 - 1) & 511;   // left wrap scalar
    int xr = (x0 + 4) & 511;   // right wrap scalar

    const float4* Uc_row = (const float4*)(Ubase + (size_t)y  * RD_W);
    const float4* Uu_row = (const float4*)(Ubase + (size_t)ym * RD_W);
    const float4* Ud_row = (const float4*)(Ubase + (size_t)yp * RD_W);
    const float4* Vc_row = (const float4*)(Vbase + (size_t)y  * RD_W);
    const float4* Vu_row = (const float4*)(Vbase + (size_t)ym * RD_W);
    const float4* Vd_row = (const float4*)(Vbase + (size_t)yp * RD_W);

    float4 Uc = Uc_row[xq];
    float4 Uu = Uu_row[xq];
    float4 Ud = Ud_row[xq];
    float  Ul = Ubase[(size_t)y * RD_W + xl];
    float  Ur = Ubase[(size_t)y * RD_W + xr];

    float4 Vc = Vc_row[xq];
    float4 Vu = Vu_row[xq];
    float4 Vd = Vd_row[xq];
    float  Vl = Vbase[(size_t)y * RD_W + xl];
    float  Vr = Vbase[(size_t)y * RD_W + xr];

    float pa = __ldg(&params[b * 3 + 0]);
    float pb = __ldg(&params[b * 3 + 1]);
    float pk = __ldg(&params[b * 3 + 2]);

    // Laplacians
    float4 lapU, lapV;
    lapU.x = (Ul   + Uc.y + Uu.x + Ud.x - 4.0f * Uc.x) * inv_dx2;
    lapU.y = (Uc.x + Uc.z + Uu.y + Ud.y - 4.0f * Uc.y) * inv_dx2;
    lapU.z = (Uc.y + Uc.w + Uu.z + Ud.z - 4.0f * Uc.z) * inv_dx2;
    lapU.w = (Uc.z + Ur   + Uu.w + Ud.w - 4.0f * Uc.w) * inv_dx2;

    lapV.x = (Vl   + Vc.y + Vu.x + Vd.x - 4.0f * Vc.x) * inv_dx2;
    lapV.y = (Vc.x + Vc.z + Vu.y + Vd.y - 4.0f * Vc.y) * inv_dx2;
    lapV.z = (Vc.y + Vc.w + Vu.z + Vd.z - 4.0f * Vc.z) * inv_dx2;
    lapV.w = (Vc.z + Vr   + Vu.w + Vd.w - 4.0f * Vc.w) * inv_dx2;

    float4 dU, dV;
    dU.x = pa * lapU.x + Uc.x - Uc.x * Uc.x * Uc.x - pk - Vc.x;
    dU.y = pa * lapU.y + Uc.y - Uc.y * Uc.y * Uc.y - pk - Vc.y;
    dU.z = pa * lapU.z + Uc.z - Uc.z * Uc.z * Uc.z - pk - Vc.z;
    dU.w = pa * lapU.w + Uc.w - Uc.w * Uc.w * Uc.w - pk - Vc.w;

    dV.x = pb * lapV.x + Uc.x - Vc.x;
    dV.y = pb * lapV.y + Uc.y - Vc.y;
    dV.z = pb * lapV.z + Uc.z - Vc.z;
    dV.w = pb * lapV.w + Uc.w - Vc.w;

    ((float4*)(OUbase + (size_t)y * RD_W))[xq] = dU;
    ((float4*)(OVbase + (size_t)y * RD_W))[xq] = dV;
}

extern "C" void kernel_launch(void* const* d_in, const int* in_sizes, int n_in,
                              void* d_out, int out_size)
{
    const float* x      = (const float*)d_in[1];
    const float* params = (const float*)d_in[2];
    float* out          = (float*)d_out;

    // 64 batches * 512 rows * 128 float4-groups = 2^22 threads
    const int threads = 256;
    const int blocks  = (64 * 512 * 128) / threads; // 16384
    react_diff_kernel<<<blocks, threads>>>(x, params, out);
}